// round 5
// baseline (speedup 1.0000x reference)
#include <cuda_runtime.h>
#include <cstdint>

// Problem constants (fixed by the dataset)
#define NB     2
#define N_SRC  131072
#define N_DST  131072
#define FDIM   64
#define EPS_F  1e-8f
#define EPW    8        // edges per warp

// Scratch: per-destination weight sums (512 KB)
__device__ float g_norm[N_DST];

// Tiny: zero g_norm (32768 float4)
__global__ void __launch_bounds__(256)
zero_norm_kernel() {
    int i = blockIdx.x * blockDim.x + threadIdx.x;
    if (i < N_DST / 4)
        reinterpret_cast<float4*>(g_norm)[i] = make_float4(0.f, 0.f, 0.f, 0.f);
}

// Fused: per-dst weight sums (one edge per thread) + zero the poisoned output.
// out4 has 8*E float4 exactly (NB*N_DST*FDIM/4 = 4194304 = 8*524288).
__global__ void __launch_bounds__(256)
norm_and_zero_kernel(const int* __restrict__ edge_index,
                     const float* __restrict__ weights,
                     float4* __restrict__ out4,
                     int E, int n4) {
    int e = blockIdx.x * blockDim.x + threadIdx.x;
    if (e < E) {
        unsigned d = (unsigned)edge_index[E + e];
        float wv = weights[e];
        if (d < N_DST) atomicAdd(&g_norm[d], wv);
    }
    float4 z = make_float4(0.f, 0.f, 0.f, 0.f);
#pragma unroll
    for (int k = 0; k < 8; k++) {
        int i = e + k * E;
        if (i < n4) out4[i] = z;
    }
}

// 8 edges per warp, front-batched loads for MLP.
// Lane layout per edge: b = lane>>4 (batch 0/1), f4 = lane&15 (float4 in F=64).
__global__ void __launch_bounds__(256)
scatter_kernel(const float* __restrict__ x,
               const int* __restrict__ edge_index,
               const float* __restrict__ weights,
               float* __restrict__ out,
               int E) {
    int warp = (blockIdx.x * blockDim.x + threadIdx.x) >> 5;
    int lane = threadIdx.x & 31;
    int e0   = warp * EPW;
    if (e0 >= E) return;

    int b  = lane >> 4;
    int f4 = lane & 15;

    // Phase 1: indices (broadcast loads)
    int s[EPW], d[EPW];
#pragma unroll
    for (int i = 0; i < EPW; i++) {
        int e = e0 + i;
        if (e < E) {
            unsigned si = (unsigned)edge_index[e];
            unsigned di = (unsigned)edge_index[E + e];
            s[i] = (si < N_SRC && di < N_DST) ? (int)si : -1;
            d[i] = (int)di;
        } else {
            s[i] = -1;
        }
    }

    // Phase 2: weights + norms (independent loads, overlap)
    float w[EPW];
#pragma unroll
    for (int i = 0; i < EPW; i++) {
        if (s[i] >= 0)
            w[i] = weights[e0 + i] / (g_norm[d[i]] + EPS_F);
    }

    // Phase 3: gather x (8 independent LDG.128 in flight per thread)
    float4 v[EPW];
#pragma unroll
    for (int i = 0; i < EPW; i++) {
        if (s[i] >= 0) {
            const float4* xrow = reinterpret_cast<const float4*>(
                x + ((size_t)b * N_SRC + (size_t)s[i]) * FDIM);
            v[i] = xrow[f4];
        }
    }

    // Phase 4: scale + vector reduction into out
#pragma unroll
    for (int i = 0; i < EPW; i++) {
        if (s[i] >= 0) {
            float4 t = v[i];
            t.x *= w[i]; t.y *= w[i]; t.z *= w[i]; t.w *= w[i];
            float4* orow = reinterpret_cast<float4*>(
                out + ((size_t)b * N_DST + (size_t)d[i]) * FDIM);
            atomicAdd(orow + f4, t);   // RED.E.ADD.F32.128
        }
    }
}

extern "C" void kernel_launch(void* const* d_in, const int* in_sizes, int n_in,
                              void* d_out, int out_size) {
    const float* x          = (const float*)d_in[0];
    const int*   edge_index = (const int*)d_in[1];
    const float* weights    = (const float*)d_in[2];
    float*       out        = (float*)d_out;

    const int E  = in_sizes[2];   // weights element count
    const int n4 = out_size / 4;

    // 1) zero norm scratch
    zero_norm_kernel<<<(N_DST / 4 + 255) / 256, 256>>>();

    // 2) fused: per-dst weight sums + zero output
    norm_and_zero_kernel<<<(E + 255) / 256, 256>>>(edge_index, weights,
                                                   (float4*)d_out, E, n4);

    // 3) normalized scatter-add SpMM: 8 edges per warp
    {
        int warps  = (E + EPW - 1) / EPW;
        int blocks = (warps * 32 + 255) / 256;
        scatter_kernel<<<blocks, 256>>>(x, edge_index, weights, out, E);
    }
}

// round 6
// speedup vs baseline: 1.3347x; 1.3347x over previous
#include <cuda_runtime.h>
#include <cstdint>

// Problem constants (fixed by the dataset)
#define NB     2
#define N_SRC  131072
#define N_DST  131072
#define FDIM   64
#define EPS_F  1e-8f
#define E_MAX  524288

#define SCAN_BLK 1024                     // elements per scan block
#define N_SCAN_BLKS (N_DST / SCAN_BLK)    // 128

// Device scratch (no allocs allowed)
__device__ float g_norm[N_DST];           // per-dst weight sums
__device__ int   g_count[N_DST];          // per-dst degree (histogram)
__device__ int   g_cursor[N_DST];         // reorder cursors
__device__ int   g_offset[N_DST];         // per-block exclusive scan of counts
__device__ int   g_bsum[N_SCAN_BLKS];     // per-scan-block totals
__device__ int   g_bsumx[N_SCAN_BLKS];    // exclusive scan of block totals
__device__ int   g_src_sorted[E_MAX];     // src indices, grouped by dst
__device__ float g_w_sorted[E_MAX];       // prenormalized weights, grouped by dst

// K1: zero the per-dst scratch
__global__ void __launch_bounds__(256)
zero_scratch_kernel() {
    int i = blockIdx.x * blockDim.x + threadIdx.x;
    if (i < N_DST) {
        g_norm[i]   = 0.0f;
        g_count[i]  = 0;
        g_cursor[i] = 0;
    }
}

// K2: histogram of dst + per-dst weight sums
__global__ void __launch_bounds__(256)
hist_kernel(const int* __restrict__ edge_index,
            const float* __restrict__ weights, int E) {
    int e = blockIdx.x * blockDim.x + threadIdx.x;
    if (e < E) {
        unsigned d = (unsigned)edge_index[E + e];
        if (d < N_DST) {
            atomicAdd(&g_count[d], 1);
            atomicAdd(&g_norm[d], weights[e]);
        }
    }
}

// K3: per-block exclusive scan of g_count (1024 elems / block, Hillis-Steele)
__global__ void __launch_bounds__(SCAN_BLK)
scan1_kernel() {
    __shared__ int sh[SCAN_BLK];
    int tid = threadIdx.x;
    int gid = blockIdx.x * SCAN_BLK + tid;
    int v = g_count[gid];
    sh[tid] = v;
    __syncthreads();
#pragma unroll
    for (int off = 1; off < SCAN_BLK; off <<= 1) {
        int t = (tid >= off) ? sh[tid - off] : 0;
        __syncthreads();
        sh[tid] += t;
        __syncthreads();
    }
    g_offset[gid] = sh[tid] - v;           // exclusive within block
    if (tid == SCAN_BLK - 1) g_bsum[blockIdx.x] = sh[tid];
}

// K4: exclusive scan of the 128 block totals (single block)
__global__ void __launch_bounds__(N_SCAN_BLKS)
scan2_kernel() {
    __shared__ int sh[N_SCAN_BLKS];
    int tid = threadIdx.x;
    int v = g_bsum[tid];
    sh[tid] = v;
    __syncthreads();
#pragma unroll
    for (int off = 1; off < N_SCAN_BLKS; off <<= 1) {
        int t = (tid >= off) ? sh[tid - off] : 0;
        __syncthreads();
        sh[tid] += t;
        __syncthreads();
    }
    g_bsumx[tid] = sh[tid] - v;
}

// K5: reorder edges into dst-grouped arrays; prenormalize weights.
__global__ void __launch_bounds__(256)
reorder_kernel(const int* __restrict__ edge_index,
               const float* __restrict__ weights, int E) {
    int e = blockIdx.x * blockDim.x + threadIdx.x;
    if (e >= E) return;
    unsigned s = (unsigned)edge_index[e];
    unsigned d = (unsigned)edge_index[E + e];
    if (s >= N_SRC || d >= N_DST) return;
    float wn = weights[e] / (g_norm[d] + EPS_F);
    int base = g_offset[d] + g_bsumx[d >> 10];
    int pos  = base + atomicAdd(&g_cursor[d], 1);
    if (pos < E_MAX) {
        g_src_sorted[pos] = (int)s;
        g_w_sorted[pos]   = wn;
    }
}

// K6: gather. One warp per destination node; both batches handled by lane split
// (b = lane>>4, f4 = lane&15). Accumulate in registers, single vector store.
// No atomics, no output zeroing needed (every out row is written).
__global__ void __launch_bounds__(256)
gather_kernel(const float* __restrict__ x, float* __restrict__ out) {
    int warp = (blockIdx.x * blockDim.x + threadIdx.x) >> 5;
    if (warp >= N_DST) return;
    int d    = warp;
    int lane = threadIdx.x & 31;
    int b    = lane >> 4;
    int f4   = lane & 15;

    int start = g_offset[d] + g_bsumx[d >> 10];
    int deg   = g_count[d];

    const float4* xb = reinterpret_cast<const float4*>(x) + (size_t)b * (N_SRC * 16);

    float4 acc = make_float4(0.f, 0.f, 0.f, 0.f);

    int j = 0;
    // unrolled by 4 for MLP on the x gathers
    for (; j + 4 <= deg; j += 4) {
        int   s0 = g_src_sorted[start + j + 0];
        int   s1 = g_src_sorted[start + j + 1];
        int   s2 = g_src_sorted[start + j + 2];
        int   s3 = g_src_sorted[start + j + 3];
        float w0 = g_w_sorted[start + j + 0];
        float w1 = g_w_sorted[start + j + 1];
        float w2 = g_w_sorted[start + j + 2];
        float w3 = g_w_sorted[start + j + 3];
        float4 v0 = xb[(size_t)s0 * 16 + f4];
        float4 v1 = xb[(size_t)s1 * 16 + f4];
        float4 v2 = xb[(size_t)s2 * 16 + f4];
        float4 v3 = xb[(size_t)s3 * 16 + f4];
        acc.x += w0 * v0.x + w1 * v1.x + w2 * v2.x + w3 * v3.x;
        acc.y += w0 * v0.y + w1 * v1.y + w2 * v2.y + w3 * v3.y;
        acc.z += w0 * v0.z + w1 * v1.z + w2 * v2.z + w3 * v3.z;
        acc.w += w0 * v0.w + w1 * v1.w + w2 * v2.w + w3 * v3.w;
    }
    for (; j < deg; j++) {
        int   s0 = g_src_sorted[start + j];
        float w0 = g_w_sorted[start + j];
        float4 v0 = xb[(size_t)s0 * 16 + f4];
        acc.x += w0 * v0.x;
        acc.y += w0 * v0.y;
        acc.z += w0 * v0.z;
        acc.w += w0 * v0.w;
    }

    float4* orow = reinterpret_cast<float4*>(
        out + ((size_t)b * N_DST + (size_t)d) * FDIM);
    orow[f4] = acc;
}

extern "C" void kernel_launch(void* const* d_in, const int* in_sizes, int n_in,
                              void* d_out, int out_size) {
    const float* x          = (const float*)d_in[0];
    const int*   edge_index = (const int*)d_in[1];
    const float* weights    = (const float*)d_in[2];
    float*       out        = (float*)d_out;

    const int E = in_sizes[2];   // weights element count (524288)

    zero_scratch_kernel<<<(N_DST + 255) / 256, 256>>>();
    hist_kernel<<<(E + 255) / 256, 256>>>(edge_index, weights, E);
    scan1_kernel<<<N_SCAN_BLKS, SCAN_BLK>>>();
    scan2_kernel<<<1, N_SCAN_BLKS>>>();
    reorder_kernel<<<(E + 255) / 256, 256>>>(edge_index, weights, E);

    {
        int warps  = N_DST;                    // one warp per dst node
        int blocks = (warps * 32) / 256;       // 16384
        gather_kernel<<<blocks, 256>>>(x, out);
    }
}

// round 8
// speedup vs baseline: 1.3686x; 1.0255x over previous
#include <cuda_runtime.h>
#include <cstdint>

// Problem constants (fixed by the dataset)
#define NB     2
#define N_SRC  131072
#define N_DST  131072
#define FDIM   64
#define EPS_F  1e-8f
#define E_MAX  524288

// Device scratch (no allocs allowed)
__device__ float  g_norm[N_DST];          // per-dst weight sums
__device__ int    g_count[N_DST];         // per-dst degree (histogram)
__device__ int    g_cursor[N_DST];        // reorder cursors
__device__ int    g_offset[N_DST];        // per-dst segment base (arbitrary order)
__device__ int    g_total;                // global allocation cursor
__device__ float2 g_edges[E_MAX];         // packed (src_as_float_bits, norm_weight)

// K1: zero the per-dst scratch + global cursor
__global__ void __launch_bounds__(256)
zero_scratch_kernel() {
    int i = blockIdx.x * blockDim.x + threadIdx.x;
    if (i < N_DST) {
        g_norm[i]   = 0.0f;
        g_count[i]  = 0;
        g_cursor[i] = 0;
    }
    if (i == 0) g_total = 0;
}

// K2: histogram of dst + per-dst weight sums
__global__ void __launch_bounds__(256)
hist_kernel(const int* __restrict__ edge_index,
            const float* __restrict__ weights, int E) {
    int e = blockIdx.x * blockDim.x + threadIdx.x;
    if (e < E) {
        unsigned d = (unsigned)edge_index[E + e];
        if (d < N_DST) {
            atomicAdd(&g_count[d], 1);
            atomicAdd(&g_norm[d], weights[e]);
        }
    }
}

// K3: allocate contiguous segment bases with warp-aggregated atomics.
// Dst-order of segments is arbitrary — gather only needs contiguity per dst.
__global__ void __launch_bounds__(256)
alloc_offsets_kernel() {
    int i = blockIdx.x * blockDim.x + threadIdx.x;
    int lane = threadIdx.x & 31;
    int c = (i < N_DST) ? g_count[i] : 0;

    // warp inclusive scan of c
    int scan = c;
#pragma unroll
    for (int off = 1; off < 32; off <<= 1) {
        int t = __shfl_up_sync(0xFFFFFFFF, scan, off);
        if (lane >= off) scan += t;
    }
    int warp_sum = __shfl_sync(0xFFFFFFFF, scan, 31);

    int warp_base = 0;
    if (lane == 31) warp_base = atomicAdd(&g_total, warp_sum);
    warp_base = __shfl_sync(0xFFFFFFFF, warp_base, 31);

    if (i < N_DST) g_offset[i] = warp_base + (scan - c);   // exclusive prefix
}

// K4: reorder edges into dst-grouped packed array; prenormalize weights.
__global__ void __launch_bounds__(256)
reorder_kernel(const int* __restrict__ edge_index,
               const float* __restrict__ weights, int E) {
    int e = blockIdx.x * blockDim.x + threadIdx.x;
    if (e >= E) return;
    unsigned s = (unsigned)edge_index[e];
    unsigned d = (unsigned)edge_index[E + e];
    if (s >= N_SRC || d >= N_DST) return;
    float wn = weights[e] / (g_norm[d] + EPS_F);
    int pos = g_offset[d] + atomicAdd(&g_cursor[d], 1);
    if (pos >= 0 && pos < E_MAX)
        g_edges[pos] = make_float2(__int_as_float((int)s), wn);
}

// K5: gather. One warp per destination node; batches split across lanes
// (b = lane>>4, f4 = lane&15). Register accumulate, single vector store.
// No atomics, no output zeroing (every out row written).
__global__ void __launch_bounds__(256)
gather_kernel(const float* __restrict__ x, float* __restrict__ out) {
    int warp = (blockIdx.x * blockDim.x + threadIdx.x) >> 5;
    if (warp >= N_DST) return;
    int d    = warp;
    int lane = threadIdx.x & 31;
    int b    = lane >> 4;
    int f4   = lane & 15;

    int start = g_offset[d];
    int deg   = g_count[d];

    const float4* xb = reinterpret_cast<const float4*>(x) + (size_t)b * (N_SRC * 16);

    float4 acc = make_float4(0.f, 0.f, 0.f, 0.f);

    int j = 0;
    for (; j + 4 <= deg; j += 4) {
        float2 e0 = g_edges[start + j + 0];
        float2 e1 = g_edges[start + j + 1];
        float2 e2 = g_edges[start + j + 2];
        float2 e3 = g_edges[start + j + 3];
        float4 v0 = xb[(size_t)__float_as_int(e0.x) * 16 + f4];
        float4 v1 = xb[(size_t)__float_as_int(e1.x) * 16 + f4];
        float4 v2 = xb[(size_t)__float_as_int(e2.x) * 16 + f4];
        float4 v3 = xb[(size_t)__float_as_int(e3.x) * 16 + f4];
        acc.x += e0.y * v0.x + e1.y * v1.x + e2.y * v2.x + e3.y * v3.x;
        acc.y += e0.y * v0.y + e1.y * v1.y + e2.y * v2.y + e3.y * v3.y;
        acc.z += e0.y * v0.z + e1.y * v1.z + e2.y * v2.z + e3.y * v3.z;
        acc.w += e0.y * v0.w + e1.y * v1.w + e2.y * v2.w + e3.y * v3.w;
    }
    for (; j < deg; j++) {
        float2 e0 = g_edges[start + j];
        float4 v0 = xb[(size_t)__float_as_int(e0.x) * 16 + f4];
        acc.x += e0.y * v0.x;
        acc.y += e0.y * v0.y;
        acc.z += e0.y * v0.z;
        acc.w += e0.y * v0.w;
    }

    float4* orow = reinterpret_cast<float4*>(
        out + ((size_t)b * N_DST + (size_t)d) * FDIM);
    orow[f4] = acc;
}

extern "C" void kernel_launch(void* const* d_in, const int* in_sizes, int n_in,
                              void* d_out, int out_size) {
    const float* x          = (const float*)d_in[0];
    const int*   edge_index = (const int*)d_in[1];
    const float* weights    = (const float*)d_in[2];
    float*       out        = (float*)d_out;

    const int E = in_sizes[2];   // weights element count (524288)

    zero_scratch_kernel<<<(N_DST + 255) / 256, 256>>>();
    hist_kernel<<<(E + 255) / 256, 256>>>(edge_index, weights, E);
    alloc_offsets_kernel<<<(N_DST + 255) / 256, 256>>>();
    reorder_kernel<<<(E + 255) / 256, 256>>>(edge_index, weights, E);

    gather_kernel<<<(N_DST * 32) / 256, 256>>>(x, out);
}